// round 1
// baseline (speedup 1.0000x reference)
#include <cuda_runtime.h>
#include <math.h>

// ---------------- problem constants (fixed shapes) ----------------
#define B_      2
#define QLEN    2048
#define KLEN    2048
#define HIDDEN_ 2048
#define NH      32
#define NKV     8
#define HD      64
#define KVREP   (NH / NKV)      // 4
#define INTER_  8192
#define MROWS   (B_ * QLEN)     // 4096

// ---------------- scratch (device globals; no allocs allowed) -----
__device__ float g_normed [(size_t)MROWS * HIDDEN_];
__device__ float g_qproj  [(size_t)MROWS * HIDDEN_];
__device__ float g_attn   [(size_t)MROWS * HIDDEN_];
__device__ float g_hidden [(size_t)MROWS * HIDDEN_];
__device__ float g_normed2[(size_t)MROWS * HIDDEN_];
__device__ float g_gate   [(size_t)MROWS * INTER_];
__device__ float g_up     [(size_t)MROWS * INTER_];
__device__ int   g_segq[QLEN];
__device__ int   g_segk[KLEN];

// ---------------- RMSNorm ----------------
__global__ __launch_bounds__(256)
void rmsnorm_kernel(const float* __restrict__ x, const float* __restrict__ w,
                    float* __restrict__ y)
{
    const int H = HIDDEN_;                 // 2048 = 512 float4
    int row = blockIdx.x;
    int tid = threadIdx.x;
    const float4* xr = (const float4*)(x + (size_t)row * H);
    float4 v0 = xr[tid];
    float4 v1 = xr[tid + 256];
    float ss = v0.x*v0.x + v0.y*v0.y + v0.z*v0.z + v0.w*v0.w
             + v1.x*v1.x + v1.y*v1.y + v1.z*v1.z + v1.w*v1.w;
    #pragma unroll
    for (int o = 16; o > 0; o >>= 1) ss += __shfl_xor_sync(0xffffffffu, ss, o);
    __shared__ float red[8];
    if ((tid & 31) == 0) red[tid >> 5] = ss;
    __syncthreads();
    float tot = 0.f;
    #pragma unroll
    for (int i = 0; i < 8; i++) tot += red[i];
    float inv = rsqrtf(tot / (float)H + 1e-5f);

    const float4* wr = (const float4*)w;
    float4 w0 = wr[tid], w1 = wr[tid + 256];
    float4 o0, o1;
    o0.x = v0.x*inv*w0.x; o0.y = v0.y*inv*w0.y; o0.z = v0.z*inv*w0.z; o0.w = v0.w*inv*w0.w;
    o1.x = v1.x*inv*w1.x; o1.y = v1.y*inv*w1.y; o1.z = v1.z*inv*w1.z; o1.w = v1.w*inv*w1.w;
    float4* yr = (float4*)(y + (size_t)row * H);
    yr[tid]       = o0;
    yr[tid + 256] = o1;
}

// ---------------- segment-id precompute ----------------
__global__ void seg_kernel(const int* __restrict__ cuq, const int* __restrict__ cuk,
                           int ncu_q, int ncu_k, int qlen, int klen,
                           int* __restrict__ segq, int* __restrict__ segk)
{
    int p = blockIdx.x * blockDim.x + threadIdx.x;
    if (p < qlen) {
        int s = 0;
        for (int i = 1; i < ncu_q; i++) s += (cuq[i] <= p);
        segq[p] = s;
    }
    if (p < klen) {
        int s = 0;
        for (int i = 1; i < ncu_k; i++) s += (cuk[i] <= p);
        segk[p] = s;
    }
}

// ---------------- GEMM: C[M,N] = A[M,K] * B[N,K]^T (+Res) ---------
// 128x128x16 tile, 256 threads, 8x8 microtile per thread.
template <int ADD_RES>
__global__ __launch_bounds__(256)
void gemm_nt(const float* __restrict__ A, const float* __restrict__ Bm,
             const float* __restrict__ Res, float* __restrict__ C,
             int M, int N, int K)
{
    const int BM = 128, BN = 128, BK = 16;
    __shared__ float As[BK][BM + 4];
    __shared__ float Bs[BK][BN + 4];
    int tid = threadIdx.x;
    int tx = tid & 15, ty = tid >> 4;
    int m0 = blockIdx.y * BM, n0 = blockIdx.x * BN;

    float acc[8][8];
    #pragma unroll
    for (int i = 0; i < 8; i++)
        #pragma unroll
        for (int j = 0; j < 8; j++) acc[i][j] = 0.f;

    for (int k0 = 0; k0 < K; k0 += BK) {
        // stage tiles (transposed into smem)
        #pragma unroll
        for (int t = 0; t < 2; t++) {
            int idx = tid + t * 256;           // 0..511
            int row = idx >> 2, kq = idx & 3;  // 128 rows x 4 float4
            float4 av = *(const float4*)(A + (size_t)(m0 + row) * K + k0 + kq * 4);
            As[kq*4+0][row] = av.x; As[kq*4+1][row] = av.y;
            As[kq*4+2][row] = av.z; As[kq*4+3][row] = av.w;
            float4 bv = *(const float4*)(Bm + (size_t)(n0 + row) * K + k0 + kq * 4);
            Bs[kq*4+0][row] = bv.x; Bs[kq*4+1][row] = bv.y;
            Bs[kq*4+2][row] = bv.z; Bs[kq*4+3][row] = bv.w;
        }
        __syncthreads();

        #pragma unroll
        for (int kk = 0; kk < BK; kk++) {
            float a[8], b[8];
            *(float4*)(a)     = *(const float4*)&As[kk][ty * 4];
            *(float4*)(a + 4) = *(const float4*)&As[kk][64 + ty * 4];
            *(float4*)(b)     = *(const float4*)&Bs[kk][tx * 4];
            *(float4*)(b + 4) = *(const float4*)&Bs[kk][64 + tx * 4];
            #pragma unroll
            for (int i = 0; i < 8; i++)
                #pragma unroll
                for (int j = 0; j < 8; j++) acc[i][j] += a[i] * b[j];
        }
        __syncthreads();
    }

    // epilogue
    #pragma unroll
    for (int i = 0; i < 8; i++) {
        int m = m0 + ((i < 4) ? (ty * 4 + i) : (64 + ty * 4 + (i - 4)));
        #pragma unroll
        for (int jh = 0; jh < 2; jh++) {
            int n = n0 + jh * 64 + tx * 4;
            float4 v;
            v.x = acc[i][jh*4+0]; v.y = acc[i][jh*4+1];
            v.z = acc[i][jh*4+2]; v.w = acc[i][jh*4+3];
            if (ADD_RES) {
                float4 r = *(const float4*)(Res + (size_t)m * N + n);
                v.x += r.x; v.y += r.y; v.z += r.z; v.w += r.w;
            }
            *(float4*)(C + (size_t)m * N + n) = v;
        }
    }
}

// ---------------- flash attention (fp32, GQA, seg+causal mask) ----
// 64 q-rows per block, 64 threads (1 row/thread), 64-key tiles in smem.
__global__ __launch_bounds__(64)
void attn_kernel(const float* __restrict__ Qp, const float* __restrict__ Kp,
                 const float* __restrict__ Vp, const int* __restrict__ segq,
                 const int* __restrict__ segk, const int* __restrict__ cuk,
                 float* __restrict__ Op, int q_len, int k_len)
{
    const int BQ = 64, BK_T = 64;
    const float scale = 0.125f;  // 1/sqrt(64)
    extern __shared__ float4 smbuf[];
    float4* Ks = smbuf;            // [64][16]
    float4* Vs = smbuf + 1024;     // [64][16]
    float4* Qs = smbuf + 2048;     // [64][17]  (padded: stride-17 avoids bank conflicts)

    int qt = blockIdx.x, h = blockIdx.y, b = blockIdx.z;
    int kvh = h / KVREP;
    int tid = threadIdx.x;
    int qrow = qt * BQ + tid;
    int off = (k_len > q_len) ? (k_len - q_len) : 0;

    // load + prescale this thread's q row
    {
        const float4* src = (const float4*)(Qp + ((size_t)(b * q_len + qrow) * NH + h) * HD);
        #pragma unroll
        for (int d4 = 0; d4 < 16; d4++) {
            float4 v = src[d4];
            v.x *= scale; v.y *= scale; v.z *= scale; v.w *= scale;
            Qs[tid * 17 + d4] = v;
        }
    }

    int myseg = segq[qrow];
    int kstart = (cuk[segq[qt * BQ]] / BK_T) * BK_T;  // same-or-earlier seg for all rows in tile
    int kend = min(k_len, qt * BQ + BQ + off);

    float4 acc4[16];
    #pragma unroll
    for (int i = 0; i < 16; i++) acc4[i] = make_float4(0.f, 0.f, 0.f, 0.f);
    float m = -1e30f, l = 0.f;

    for (int k0 = kstart; k0 < kend; k0 += BK_T) {
        __syncthreads();
        // cooperative K/V tile load (coalesced: 4 rows x 16 float4 per pass)
        for (int i = tid; i < BK_T * 16; i += 64) {
            int r = i >> 4, d4 = i & 15;
            size_t base = ((size_t)(b * k_len + k0 + r) * NKV + kvh) * HD;
            Ks[r * 16 + d4] = ((const float4*)(Kp + base))[d4];
            Vs[r * 16 + d4] = ((const float4*)(Vp + base))[d4];
        }
        __syncthreads();

        float s[BK_T];
        #pragma unroll
        for (int kk = 0; kk < BK_T; kk++) s[kk] = 0.f;
        for (int d4 = 0; d4 < 16; d4++) {
            float4 q4 = Qs[tid * 17 + d4];
            #pragma unroll
            for (int kk = 0; kk < BK_T; kk++) {
                float4 k4 = Ks[kk * 16 + d4];     // broadcast LDS
                s[kk] += q4.x * k4.x + q4.y * k4.y + q4.z * k4.z + q4.w * k4.w;
            }
        }

        // mask
        float tmax = -1e30f;
        #pragma unroll
        for (int kk = 0; kk < BK_T; kk++) {
            int kg = k0 + kk;
            bool ok = (kg < k_len) && (kg <= qrow + off) && (segk[kg] == myseg);
            s[kk] = ok ? s[kk] : -1e30f;
            tmax = fmaxf(tmax, s[kk]);
        }
        if (tmax > -1e29f) {
            float mnew = fmaxf(m, tmax);
            float corr = __expf(m - mnew);        // m=-1e30 -> 0
            l *= corr;
            #pragma unroll
            for (int i = 0; i < 16; i++) {
                acc4[i].x *= corr; acc4[i].y *= corr;
                acc4[i].z *= corr; acc4[i].w *= corr;
            }
            #pragma unroll
            for (int kk = 0; kk < BK_T; kk++) {
                float p = __expf(s[kk] - mnew);   // masked -> 0
                l += p;
                #pragma unroll
                for (int d4 = 0; d4 < 16; d4++) {
                    float4 v4 = Vs[kk * 16 + d4]; // broadcast LDS
                    acc4[d4].x += p * v4.x; acc4[d4].y += p * v4.y;
                    acc4[d4].z += p * v4.z; acc4[d4].w += p * v4.w;
                }
            }
            m = mnew;
        }
    }

    float inv = 1.f / l;   // causal diagonal guarantees l > 0
    float4* dst = (float4*)(Op + ((size_t)(b * q_len + qrow) * NH + h) * HD);
    #pragma unroll
    for (int d4 = 0; d4 < 16; d4++) {
        float4 v = acc4[d4];
        v.x *= inv; v.y *= inv; v.z *= inv; v.w *= inv;
        dst[d4] = v;
    }
}

// ---------------- silu(gate) * up ----------------
__global__ __launch_bounds__(256)
void silu_mul_kernel(const float* __restrict__ g, const float* __restrict__ u,
                     float* __restrict__ o, size_t n4)
{
    size_t i = (size_t)blockIdx.x * blockDim.x + threadIdx.x;
    if (i >= n4) return;
    float4 gv = ((const float4*)g)[i];
    float4 uv = ((const float4*)u)[i];
    float4 ov;
    ov.x = gv.x / (1.f + __expf(-gv.x)) * uv.x;
    ov.y = gv.y / (1.f + __expf(-gv.y)) * uv.y;
    ov.z = gv.z / (1.f + __expf(-gv.z)) * uv.z;
    ov.w = gv.w / (1.f + __expf(-gv.w)) * uv.w;
    ((float4*)o)[i] = ov;
}

// ---------------- launch ----------------
extern "C" void kernel_launch(void* const* d_in, const int* in_sizes, int n_in,
                              void* d_out, int out_size)
{
    const float* hs   = (const float*)d_in[0];
    const float* kst  = (const float*)d_in[1];
    const float* vst  = (const float*)d_in[2];
    // d_in[3] = gmu_memory (unused)
    const float* wln1 = (const float*)d_in[4];
    const float* wln2 = (const float*)d_in[5];
    const float* wq   = (const float*)d_in[6];
    const float* wo   = (const float*)d_in[7];
    const float* wg   = (const float*)d_in[8];
    const float* wu   = (const float*)d_in[9];
    const float* wd   = (const float*)d_in[10];
    const int* cuq    = (const int*)d_in[11];
    const int* cuk    = (const int*)d_in[12];
    int ncu_q = in_sizes[11], ncu_k = in_sizes[12];
    float* out = (float*)d_out;

    float *normed, *qproj, *attn, *hidden, *normed2, *gate, *up;
    int *segq, *segk;
    cudaGetSymbolAddress((void**)&normed,  g_normed);
    cudaGetSymbolAddress((void**)&qproj,   g_qproj);
    cudaGetSymbolAddress((void**)&attn,    g_attn);
    cudaGetSymbolAddress((void**)&hidden,  g_hidden);
    cudaGetSymbolAddress((void**)&normed2, g_normed2);
    cudaGetSymbolAddress((void**)&gate,    g_gate);
    cudaGetSymbolAddress((void**)&up,      g_up);
    cudaGetSymbolAddress((void**)&segq,    g_segq);
    cudaGetSymbolAddress((void**)&segk,    g_segk);

    const int ATTN_SMEM = (1024 + 1024 + 64 * 17) * 16;  // 50176 bytes
    cudaFuncSetAttribute(attn_kernel, cudaFuncAttributeMaxDynamicSharedMemorySize, ATTN_SMEM);

    // 1) ln1
    rmsnorm_kernel<<<MROWS, 256>>>(hs, wln1, normed);
    // 2) q projection
    gemm_nt<0><<<dim3(HIDDEN_ / 128, MROWS / 128), 256>>>(normed, wq, nullptr, qproj,
                                                          MROWS, HIDDEN_, HIDDEN_);
    // 3) segment ids
    seg_kernel<<<(QLEN > KLEN ? QLEN : KLEN + 255) / 256 + 1, 256>>>(
        cuq, cuk, ncu_q, ncu_k, QLEN, KLEN, segq, segk);
    // 4) attention
    attn_kernel<<<dim3(QLEN / 64, NH, B_), 64, ATTN_SMEM>>>(
        qproj, kst, vst, segq, segk, cuk, attn, QLEN, KLEN);
    // 5) o projection + residual
    gemm_nt<1><<<dim3(HIDDEN_ / 128, MROWS / 128), 256>>>(attn, wo, hs, hidden,
                                                          MROWS, HIDDEN_, HIDDEN_);
    // 6) ln2
    rmsnorm_kernel<<<MROWS, 256>>>(hidden, wln2, normed2);
    // 7) gate / up projections
    gemm_nt<0><<<dim3(INTER_ / 128, MROWS / 128), 256>>>(normed2, wg, nullptr, gate,
                                                         MROWS, INTER_, HIDDEN_);
    gemm_nt<0><<<dim3(INTER_ / 128, MROWS / 128), 256>>>(normed2, wu, nullptr, up,
                                                         MROWS, INTER_, HIDDEN_);
    // 8) silu(gate) * up  (in place into gate)
    silu_mul_kernel<<<(unsigned)(((size_t)MROWS * INTER_ / 4 + 255) / 256), 256>>>(
        gate, up, gate, (size_t)MROWS * INTER_ / 4);
    // 9) down projection + residual -> output
    gemm_nt<1><<<dim3(HIDDEN_ / 128, MROWS / 128), 256>>>(gate, wd, hidden, out,
                                                          MROWS, HIDDEN_, INTER_);
}

// round 11
// speedup vs baseline: 2.0480x; 2.0480x over previous
#include <cuda_runtime.h>
#include <cuda_bf16.h>
#include <cstdint>
#include <math.h>

// ---------------- problem constants ----------------
#define B_      2
#define QLEN    2048
#define KLEN    2048
#define HIDDEN_ 2048
#define NH      32
#define NKV     8
#define HD      64
#define KVREP   (NH / NKV)
#define INTER_  8192
#define MROWS   (B_ * QLEN)     // 4096

// ---------------- scratch (device globals) ----------------
__device__ float g_qproj  [(size_t)MROWS * HIDDEN_];
__device__ float g_attn   [(size_t)MROWS * HIDDEN_];
__device__ float g_hidden [(size_t)MROWS * HIDDEN_];
__device__ float g_gate   [(size_t)MROWS * INTER_];
__device__ float g_up     [(size_t)MROWS * INTER_];
__device__ int   g_segq[QLEN];
__device__ int   g_segk[KLEN];
// converted (hi/lo interleaved per 32-elem chunk) bf16 operands, row width = 2*K
__device__ __nv_bfloat16 c_wq  [(size_t)HIDDEN_ * 2 * HIDDEN_];
__device__ __nv_bfloat16 c_wo  [(size_t)HIDDEN_ * 2 * HIDDEN_];
__device__ __nv_bfloat16 c_wg  [(size_t)INTER_  * 2 * HIDDEN_];
__device__ __nv_bfloat16 c_wu  [(size_t)INTER_  * 2 * HIDDEN_];
__device__ __nv_bfloat16 c_wd  [(size_t)HIDDEN_ * 2 * INTER_];
__device__ __nv_bfloat16 c_normed [(size_t)MROWS * 2 * HIDDEN_];
__device__ __nv_bfloat16 c_attn   [(size_t)MROWS * 2 * HIDDEN_];
__device__ __nv_bfloat16 c_normed2[(size_t)MROWS * 2 * HIDDEN_];
__device__ __nv_bfloat16 c_act    [(size_t)MROWS * 2 * INTER_];

// ---------------- helpers ----------------
__device__ __forceinline__ uint32_t smem_to_u32(const void* p) {
    uint32_t a;
    asm("{ .reg .u64 t; cvta.to.shared.u64 t, %1; cvt.u32.u64 %0, t; }" : "=r"(a) : "l"(p));
    return a;
}
__device__ __forceinline__ uint32_t pack2(__nv_bfloat16 a, __nv_bfloat16 b) {
    return (uint32_t)__bfloat16_as_ushort(a) | ((uint32_t)__bfloat16_as_ushort(b) << 16);
}
__device__ __forceinline__ void split_store(__nv_bfloat16* rowbase, int e, float4 v) {
    int off = ((e >> 5) << 6) + (e & 31);
    __nv_bfloat16 h0 = __float2bfloat16_rn(v.x), h1 = __float2bfloat16_rn(v.y),
                  h2 = __float2bfloat16_rn(v.z), h3 = __float2bfloat16_rn(v.w);
    float l0 = v.x - __bfloat162float(h0), l1 = v.y - __bfloat162float(h1),
          l2 = v.z - __bfloat162float(h2), l3 = v.w - __bfloat162float(h3);
    uint2 hu, lu;
    hu.x = pack2(h0, h1); hu.y = pack2(h2, h3);
    lu.x = pack2(__float2bfloat16_rn(l0), __float2bfloat16_rn(l1));
    lu.y = pack2(__float2bfloat16_rn(l2), __float2bfloat16_rn(l3));
    *(uint2*)(rowbase + off)      = hu;
    *(uint2*)(rowbase + off + 32) = lu;
}

// ---------------- converters ----------------
__global__ __launch_bounds__(256)
void convert_split(const float* __restrict__ x, __nv_bfloat16* __restrict__ y, int kshift) {
    size_t gid = (size_t)blockIdx.x * 256 + threadIdx.x;
    size_t e = gid * 4;
    size_t row = e >> kshift;
    int k = (int)(e & (((size_t)1 << kshift) - 1));
    float4 v = *(const float4*)(x + e);
    split_store(y + (row << (kshift + 1)), k, v);
}

__global__ __launch_bounds__(256)
void silu_conv(const float* __restrict__ g, const float* __restrict__ u,
               __nv_bfloat16* __restrict__ y) {
    size_t gid = (size_t)blockIdx.x * 256 + threadIdx.x;
    size_t e = gid * 4;
    size_t row = e >> 13;
    int k = (int)(e & 8191);
    float4 gv = *(const float4*)(g + e);
    float4 uv = *(const float4*)(u + e);
    float4 v;
    v.x = gv.x / (1.f + __expf(-gv.x)) * uv.x;
    v.y = gv.y / (1.f + __expf(-gv.y)) * uv.y;
    v.z = gv.z / (1.f + __expf(-gv.z)) * uv.z;
    v.w = gv.w / (1.f + __expf(-gv.w)) * uv.w;
    split_store(y + row * (2 * INTER_), k, v);
}

// ---------------- RMSNorm (fused hi/lo split output) ----------------
__global__ __launch_bounds__(256)
void rmsnorm_conv(const float* __restrict__ x, const float* __restrict__ w,
                  __nv_bfloat16* __restrict__ y) {
    int row = blockIdx.x, tid = threadIdx.x;
    const float4* xr = (const float4*)(x + (size_t)row * HIDDEN_);
    float4 v0 = xr[tid], v1 = xr[tid + 256];
    float ss = v0.x*v0.x + v0.y*v0.y + v0.z*v0.z + v0.w*v0.w
             + v1.x*v1.x + v1.y*v1.y + v1.z*v1.z + v1.w*v1.w;
    #pragma unroll
    for (int o = 16; o > 0; o >>= 1) ss += __shfl_xor_sync(0xffffffffu, ss, o);
    __shared__ float red[8];
    if ((tid & 31) == 0) red[tid >> 5] = ss;
    __syncthreads();
    float tot = 0.f;
    #pragma unroll
    for (int i = 0; i < 8; i++) tot += red[i];
    float inv = rsqrtf(tot / (float)HIDDEN_ + 1e-5f);
    const float4* wr = (const float4*)w;
    float4 w0 = wr[tid], w1 = wr[tid + 256];
    float4 o0, o1;
    o0.x = v0.x*inv*w0.x; o0.y = v0.y*inv*w0.y; o0.z = v0.z*inv*w0.z; o0.w = v0.w*inv*w0.w;
    o1.x = v1.x*inv*w1.x; o1.y = v1.y*inv*w1.y; o1.z = v1.z*inv*w1.z; o1.w = v1.w*inv*w1.w;
    __nv_bfloat16* rb = y + (size_t)row * (2 * HIDDEN_);
    split_store(rb, tid * 4, o0);
    split_store(rb, tid * 4 + 1024, o1);
}

// ---------------- segment ids ----------------
__global__ void seg_kernel(const int* __restrict__ cuq, const int* __restrict__ cuk,
                           int ncu_q, int ncu_k, int* __restrict__ segq, int* __restrict__ segk) {
    int p = blockIdx.x * blockDim.x + threadIdx.x;
    if (p < QLEN) {
        int s = 0;
        for (int i = 1; i < ncu_q; i++) s += (cuq[i] <= p);
        segq[p] = s;
    }
    if (p < KLEN) {
        int s = 0;
        for (int i = 1; i < ncu_k; i++) s += (cuk[i] <= p);
        segk[p] = s;
    }
}

// ---------------- HMMA bf16x3 GEMM: C = A * B^T (+Res) ----------------
// Converted layout per row: per 32-elem chunk, 64 bf16 = [hi(32) | lo(32)] = 128B.
// Tile 128x128, 8 warps (2M x 4N), warp tile 64x32 via mma.sync.m16n8k16.
// SMEM per stage: A 128 rows x 144B + B 128 rows x 144B (128B data + 16B pad;
// pad makes the fragment LDS pattern perfectly bank-conflict-free).
#define NSTG 3
#define ROWSPAN 144
#define OP_BYTES (128 * ROWSPAN)       // 18432
#define STG_BYTES (2 * OP_BYTES)       // 36864

__device__ __forceinline__ void stage_load(uint32_t sbase, int s, const char* Ab,
                                           const char* Bb, size_t rowB, int tid) {
    uint32_t so = sbase + s * STG_BYTES;
    #pragma unroll
    for (int it = 0; it < 8; it++) {
        int lin = it * 256 + tid;          // 0..2047 units of 16B
        int op  = lin >> 10;               // 0: A, 1: B
        int u   = lin & 1023;
        int row = u >> 3;
        int cb  = (u & 7) << 4;
        uint32_t dst = so + op * OP_BYTES + row * ROWSPAN + cb;
        const char* src = (op ? Bb : Ab) + (size_t)row * rowB + cb;
        asm volatile("cp.async.cg.shared.global [%0], [%1], 16;" :: "r"(dst), "l"(src));
    }
    asm volatile("cp.async.commit_group;" ::: "memory");
}

__device__ __forceinline__ void mma_bf16(float c[4], uint32_t a0, uint32_t a1,
                                         uint32_t a2, uint32_t a3,
                                         uint32_t b0, uint32_t b1) {
    asm volatile(
        "mma.sync.aligned.m16n8k16.row.col.f32.bf16.bf16.f32 "
        "{%0,%1,%2,%3}, {%4,%5,%6,%7}, {%8,%9}, {%0,%1,%2,%3};"
        : "+f"(c[0]), "+f"(c[1]), "+f"(c[2]), "+f"(c[3])
        : "r"(a0), "r"(a1), "r"(a2), "r"(a3), "r"(b0), "r"(b1));
}

__global__ __launch_bounds__(256)
void gemm_mma(const __nv_bfloat16* __restrict__ Ac, const __nv_bfloat16* __restrict__ Bc,
              const float* __restrict__ Res, float* __restrict__ C, int M, int N, int K) {
    extern __shared__ __align__(128) char smem[];
    uint32_t sbase = smem_to_u32(smem);
    int tid = threadIdx.x, wid = tid >> 5, lane = tid & 31;
    int g = lane >> 2, t = lane & 3;
    int wm = wid >> 2, wn = wid & 3;      // warp grid 2(M) x 4(N)
    int m0 = blockIdx.y * 128, n0 = blockIdx.x * 128;
    size_t rowB = (size_t)K * 4;          // bytes per converted row (2K bf16)

    float acc[4][4][4];
    #pragma unroll
    for (int i = 0; i < 4; i++)
        #pragma unroll
        for (int j = 0; j < 4; j++)
            #pragma unroll
            for (int q = 0; q < 4; q++) acc[i][j][q] = 0.f;

    const char* Ab0 = (const char*)Ac + (size_t)m0 * rowB;
    const char* Bb0 = (const char*)Bc + (size_t)n0 * rowB;
    int niters = K >> 5;                  // one 128B chunk per iter

    stage_load(sbase, 0, Ab0, Bb0, rowB, tid);
    stage_load(sbase, 1, Ab0 + 128, Bb0 + 128, rowB, tid);

    // bf16x3 product schedule: byte-offsets of the 16-elem column groups
    // within a chunk row [hi0 hi1 lo0 lo1] at bytes {0,32,64,96}:
    // AhBh:(0,0),(32,32)  AhBl:(0,64),(32,96)  AlBh:(64,0),(96,32)
    const int PA[6] = {0, 32, 0, 32, 64, 96};
    const int PB[6] = {0, 32, 64, 96, 0, 32};

    for (int j = 0; j < niters; j++) {
        if (j < niters - 1) asm volatile("cp.async.wait_group 1;" ::: "memory");
        else                asm volatile("cp.async.wait_group 0;" ::: "memory");
        __syncthreads();

        int jn = j + 2;
        if (jn < niters)
            stage_load(sbase, jn % NSTG, Ab0 + (size_t)jn * 128, Bb0 + (size_t)jn * 128, rowB, tid);

        const char* sA = smem + (j % NSTG) * STG_BYTES;
        const char* sB = sA + OP_BYTES;

        #pragma unroll
        for (int p = 0; p < 6; p++) {
            int ab = PA[p], bb = PB[p];
            uint32_t af[4][4], bf[4][2];
            #pragma unroll
            for (int mi = 0; mi < 4; mi++) {
                int r0 = (wm * 64 + mi * 16 + g) * ROWSPAN;
                int r1 = r0 + 8 * ROWSPAN;
                af[mi][0] = *(const uint32_t*)(sA + r0 + ab + t * 4);
                af[mi][1] = *(const uint32_t*)(sA + r1 + ab + t * 4);
                af[mi][2] = *(const uint32_t*)(sA + r0 + ab + 16 + t * 4);
                af[mi][3] = *(const uint32_t*)(sA + r1 + ab + 16 + t * 4);
            }
            #pragma unroll
            for (int ni = 0; ni < 4; ni++) {
                int rn = (wn * 32 + ni * 8 + g) * ROWSPAN;
                bf[ni][0] = *(const uint32_t*)(sB + rn + bb + t * 4);
                bf[ni][1] = *(const uint32_t*)(sB + rn + bb + 16 + t * 4);
            }
            #pragma unroll
            for (int mi = 0; mi < 4; mi++)
                #pragma unroll
                for (int ni = 0; ni < 4; ni++)
                    mma_bf16(acc[mi][ni], af[mi][0], af[mi][1], af[mi][2], af[mi][3],
                             bf[ni][0], bf[ni][1]);
        }
        __syncthreads();
    }

    // epilogue: warp writes its 64x32 region
    #pragma unroll
    for (int mi = 0; mi < 4; mi++) {
        int grow0 = m0 + wm * 64 + mi * 16 + g;
        int grow1 = grow0 + 8;
        #pragma unroll
        for (int ni = 0; ni < 4; ni++) {
            int gcol = n0 + wn * 32 + ni * 8 + t * 2;
            float2 v0 = make_float2(acc[mi][ni][0], acc[mi][ni][1]);
            float2 v1 = make_float2(acc[mi][ni][2], acc[mi][ni][3]);
            if (Res) {
                float2 r0 = *(const float2*)(Res + (size_t)grow0 * N + gcol);
                float2 r1 = *(const float2*)(Res + (size_t)grow1 * N + gcol);
                v0.x += r0.x; v0.y += r0.y;
                v1.x += r1.x; v1.y += r1.y;
            }
            *(float2*)(C + (size_t)grow0 * N + gcol) = v0;
            *(float2*)(C + (size_t)grow1 * N + gcol) = v1;
        }
    }
}

// ---------------- flash attention (unchanged, known-passing) ----------------
__global__ __launch_bounds__(64)
void attn_kernel(const float* __restrict__ Qp, const float* __restrict__ Kp,
                 const float* __restrict__ Vp, const int* __restrict__ segq,
                 const int* __restrict__ segk, const int* __restrict__ cuk,
                 float* __restrict__ Op, int q_len, int k_len)
{
    const int BQ = 64, BK_T = 64;
    const float scale = 0.125f;
    extern __shared__ float4 smbuf[];
    float4* Ks = smbuf;
    float4* Vs = smbuf + 1024;
    float4* Qs = smbuf + 2048;

    int qt = blockIdx.x, h = blockIdx.y, b = blockIdx.z;
    int kvh = h / KVREP;
    int tid = threadIdx.x;
    int qrow = qt * BQ + tid;
    int off = (k_len > q_len) ? (k_len - q_len) : 0;

    {
        const float4* src = (const float4*)(Qp + ((size_t)(b * q_len + qrow) * NH + h) * HD);
        #pragma unroll
        for (int d4 = 0; d4 < 16; d4++) {
            float4 v = src[d4];
            v.x *= scale; v.y *= scale; v.z *= scale; v.w *= scale;
            Qs[tid * 17 + d4] = v;
        }
    }

    int myseg = segq[qrow];
    int kstart = (cuk[segq[qt * BQ]] / BK_T) * BK_T;
    int kend = min(k_len, qt * BQ + BQ + off);

    float4 acc4[16];
    #pragma unroll
    for (int i = 0; i < 16; i++) acc4[i] = make_float4(0.f, 0.f, 0.f, 0.f);
    float m = -1e30f, l = 0.f;

    for (int k0 = kstart; k0 < kend; k0 += BK_T) {
        __syncthreads();
        for (int i = tid; i < BK_T * 16; i += 64) {
            int r = i >> 4, d4 = i & 15;
            size_t base = ((size_t)(b * k_len + k0 + r) * NKV + kvh) * HD;
            Ks[r * 16 + d4] = ((const float4*)(Kp + base))[d4];
            Vs[r * 16 + d4] = ((const float4*)(Vp + base))[d4];
        }
        __syncthreads();

        float s[BK_T];
        #pragma unroll
        for (int kk = 0; kk < BK_T; kk++) s[kk] = 0.f;
        for (int d4 = 0; d4 < 16; d4++) {
            float4 q4 = Qs[tid * 17 + d4];
            #pragma unroll
            for (int kk = 0; kk < BK_T; kk++) {
                float4 k4 = Ks[kk * 16 + d4];
                s[kk] += q4.x * k4.x + q4.y * k4.y + q4.z * k4.z + q4.w * k4.w;
            }
        }

        float tmax = -1e30f;
        #pragma unroll
        for (int kk = 0; kk < BK_T; kk++) {
            int kg = k0 + kk;
            bool ok = (kg < k_len) && (kg <= qrow + off) && (segk[kg] == myseg);
            s[kk] = ok ? s[kk] : -1e30f;
            tmax = fmaxf(tmax, s[kk]);
        }
        if (tmax > -1e29f) {
            float mnew = fmaxf(m, tmax);
            float corr = __expf(m - mnew);
            l *= corr;
            #pragma unroll
            for (int i = 0; i < 16; i++) {
                acc4[i].x *= corr; acc4[i].y *= corr;
                acc4[i].z *= corr; acc4[i].w *= corr;
            }
            #pragma unroll
            for (int kk = 0; kk < BK_T; kk++) {
                float p = __expf(s[kk] - mnew);
                l += p;
                #pragma unroll
                for (int d4 = 0; d4 < 16; d4++) {
                    float4 v4 = Vs[kk * 16 + d4];
                    acc4[d4].x += p * v4.x; acc4[d4].y += p * v4.y;
                    acc4[d4].z += p * v4.z; acc4[d4].w += p * v4.w;
                }
            }
            m = mnew;
        }
    }

    float inv = 1.f / l;
    float4* dst = (float4*)(Op + ((size_t)(b * q_len + qrow) * NH + h) * HD);
    #pragma unroll
    for (int d4 = 0; d4 < 16; d4++) {
        float4 v = acc4[d4];
        v.x *= inv; v.y *= inv; v.z *= inv; v.w *= inv;
        dst[d4] = v;
    }
}

// ---------------- launch ----------------
extern "C" void kernel_launch(void* const* d_in, const int* in_sizes, int n_in,
                              void* d_out, int out_size)
{
    const float* hs   = (const float*)d_in[0];
    const float* kst  = (const float*)d_in[1];
    const float* vst  = (const float*)d_in[2];
    const float* wln1 = (const float*)d_in[4];
    const float* wln2 = (const float*)d_in[5];
    const float* wq   = (const float*)d_in[6];
    const float* wo   = (const float*)d_in[7];
    const float* wg   = (const float*)d_in[8];
    const float* wu   = (const float*)d_in[9];
    const float* wd   = (const float*)d_in[10];
    const int* cuq    = (const int*)d_in[11];
    const int* cuk    = (const int*)d_in[12];
    int ncu_q = in_sizes[11], ncu_k = in_sizes[12];
    float* out = (float*)d_out;

    float *qproj, *attn, *hidden, *gate, *up;
    int *segq, *segk;
    __nv_bfloat16 *cwq, *cwo, *cwg, *cwu, *cwd, *cn1, *cat, *cn2, *cac;
    cudaGetSymbolAddress((void**)&qproj,  g_qproj);
    cudaGetSymbolAddress((void**)&attn,   g_attn);
    cudaGetSymbolAddress((void**)&hidden, g_hidden);
    cudaGetSymbolAddress((void**)&gate,   g_gate);
    cudaGetSymbolAddress((void**)&up,     g_up);
    cudaGetSymbolAddress((void**)&segq,   g_segq);
    cudaGetSymbolAddress((void**)&segk,   g_segk);
    cudaGetSymbolAddress((void**)&cwq, c_wq);
    cudaGetSymbolAddress((void**)&cwo, c_wo);
    cudaGetSymbolAddress((void**)&cwg, c_wg);
    cudaGetSymbolAddress((void**)&cwu, c_wu);
    cudaGetSymbolAddress((void**)&cwd, c_wd);
    cudaGetSymbolAddress((void**)&cn1, c_normed);
    cudaGetSymbolAddress((void**)&cat, c_attn);
    cudaGetSymbolAddress((void**)&cn2, c_normed2);
    cudaGetSymbolAddress((void**)&cac, c_act);

    const int GEMM_SMEM = NSTG * STG_BYTES;   // 110592
    cudaFuncSetAttribute(gemm_mma, cudaFuncAttributeMaxDynamicSharedMemorySize, GEMM_SMEM);
    const int ATTN_SMEM = (1024 + 1024 + 64 * 17) * 16;
    cudaFuncSetAttribute(attn_kernel, cudaFuncAttributeMaxDynamicSharedMemorySize, ATTN_SMEM);

    // weight conversions (hi/lo bf16 split, interleaved)
    convert_split<<< (HIDDEN_ * HIDDEN_) / 1024, 256 >>>(wq, cwq, 11);
    convert_split<<< (HIDDEN_ * HIDDEN_) / 1024, 256 >>>(wo, cwo, 11);
    convert_split<<< (INTER_  * HIDDEN_) / 1024, 256 >>>(wg, cwg, 11);
    convert_split<<< (INTER_  * HIDDEN_) / 1024, 256 >>>(wu, cwu, 11);
    convert_split<<< (HIDDEN_ * INTER_ ) / 1024, 256 >>>(wd, cwd, 13);

    // ln1 (fused split)
    rmsnorm_conv<<<MROWS, 256>>>(hs, wln1, cn1);
    // q projection
    gemm_mma<<<dim3(HIDDEN_ / 128, MROWS / 128), 256, GEMM_SMEM>>>(
        cn1, cwq, nullptr, qproj, MROWS, HIDDEN_, HIDDEN_);
    // segment ids
    seg_kernel<<<(QLEN + 255) / 256, 256>>>(cuq, cuk, ncu_q, ncu_k, segq, segk);
    // attention
    attn_kernel<<<dim3(QLEN / 64, NH, B_), 64, ATTN_SMEM>>>(
        qproj, kst, vst, segq, segk, cuk, attn, QLEN, KLEN);
    // o projection + residual
    convert_split<<< (MROWS * HIDDEN_) / 1024, 256 >>>(attn, cat, 11);
    gemm_mma<<<dim3(HIDDEN_ / 128, MROWS / 128), 256, GEMM_SMEM>>>(
        cat, cwo, hs, hidden, MROWS, HIDDEN_, HIDDEN_);
    // ln2 (fused split)
    rmsnorm_conv<<<MROWS, 256>>>(hidden, wln2, cn2);
    // gate / up projections
    gemm_mma<<<dim3(INTER_ / 128, MROWS / 128), 256, GEMM_SMEM>>>(
        cn2, cwg, nullptr, gate, MROWS, INTER_, HIDDEN_);
    gemm_mma<<<dim3(INTER_ / 128, MROWS / 128), 256, GEMM_SMEM>>>(
        cn2, cwu, nullptr, up, MROWS, INTER_, HIDDEN_);
    // silu(gate)*up (fused split)
    silu_conv<<< (int)(((size_t)MROWS * INTER_) / 1024), 256 >>>(gate, up, cac);
    // down projection + residual -> out
    gemm_mma<<<dim3(HIDDEN_ / 128, MROWS / 128), 256, GEMM_SMEM>>>(
        cac, cwd, hidden, out, MROWS, HIDDEN_, INTER_);
}

// round 14
// speedup vs baseline: 2.1029x; 1.0268x over previous
#include <cuda_runtime.h>
#include <cuda_bf16.h>
#include <cstdint>
#include <math.h>

// ---------------- problem constants ----------------
#define B_      2
#define QLEN    2048
#define KLEN    2048
#define HIDDEN_ 2048
#define NH      32
#define NKV     8
#define HD      64
#define KVREP   (NH / NKV)
#define INTER_  8192
#define MROWS   (B_ * QLEN)     // 4096

// ---------------- scratch (device globals) ----------------
__device__ float g_qproj  [(size_t)MROWS * HIDDEN_];
__device__ float g_attn   [(size_t)MROWS * HIDDEN_];
__device__ float g_hidden [(size_t)MROWS * HIDDEN_];
__device__ float g_gate   [(size_t)MROWS * INTER_];
__device__ float g_up     [(size_t)MROWS * INTER_];
__device__ int   g_segq[QLEN];
__device__ int   g_segk[KLEN];
// converted (hi/lo interleaved per 32-elem chunk) bf16 operands, row width = 2*K
__device__ __nv_bfloat16 c_wq  [(size_t)HIDDEN_ * 2 * HIDDEN_];
__device__ __nv_bfloat16 c_wo  [(size_t)HIDDEN_ * 2 * HIDDEN_];
__device__ __nv_bfloat16 c_wg  [(size_t)INTER_  * 2 * HIDDEN_];
__device__ __nv_bfloat16 c_wu  [(size_t)INTER_  * 2 * HIDDEN_];
__device__ __nv_bfloat16 c_wd  [(size_t)HIDDEN_ * 2 * INTER_];
__device__ __nv_bfloat16 c_normed [(size_t)MROWS * 2 * HIDDEN_];
__device__ __nv_bfloat16 c_attn   [(size_t)MROWS * 2 * HIDDEN_];
__device__ __nv_bfloat16 c_normed2[(size_t)MROWS * 2 * HIDDEN_];
__device__ __nv_bfloat16 c_act    [(size_t)MROWS * 2 * INTER_];

// ---------------- helpers ----------------
__device__ __forceinline__ uint32_t smem_to_u32(const void* p) {
    uint32_t a;
    asm("{ .reg .u64 t; cvta.to.shared.u64 t, %1; cvt.u32.u64 %0, t; }" : "=r"(a) : "l"(p));
    return a;
}
__device__ __forceinline__ uint32_t pack2(__nv_bfloat16 a, __nv_bfloat16 b) {
    return (uint32_t)__bfloat16_as_ushort(a) | ((uint32_t)__bfloat16_as_ushort(b) << 16);
}
__device__ __forceinline__ void split_store(__nv_bfloat16* rowbase, int e, float4 v) {
    int off = ((e >> 5) << 6) + (e & 31);
    __nv_bfloat16 h0 = __float2bfloat16_rn(v.x), h1 = __float2bfloat16_rn(v.y),
                  h2 = __float2bfloat16_rn(v.z), h3 = __float2bfloat16_rn(v.w);
    float l0 = v.x - __bfloat162float(h0), l1 = v.y - __bfloat162float(h1),
          l2 = v.z - __bfloat162float(h2), l3 = v.w - __bfloat162float(h3);
    uint2 hu, lu;
    hu.x = pack2(h0, h1); hu.y = pack2(h2, h3);
    lu.x = pack2(__float2bfloat16_rn(l0), __float2bfloat16_rn(l1));
    lu.y = pack2(__float2bfloat16_rn(l2), __float2bfloat16_rn(l3));
    *(uint2*)(rowbase + off)      = hu;
    *(uint2*)(rowbase + off + 32) = lu;
}

// ---------------- converters ----------------
__global__ __launch_bounds__(256)
void convert_split(const float* __restrict__ x, __nv_bfloat16* __restrict__ y, int kshift) {
    size_t gid = (size_t)blockIdx.x * 256 + threadIdx.x;
    size_t e = gid * 4;
    size_t row = e >> kshift;
    int k = (int)(e & (((size_t)1 << kshift) - 1));
    float4 v = *(const float4*)(x + e);
    split_store(y + (row << (kshift + 1)), k, v);
}

__global__ __launch_bounds__(256)
void silu_conv(const float* __restrict__ g, const float* __restrict__ u,
               __nv_bfloat16* __restrict__ y) {
    size_t gid = (size_t)blockIdx.x * 256 + threadIdx.x;
    size_t e = gid * 4;
    size_t row = e >> 13;
    int k = (int)(e & 8191);
    float4 gv = *(const float4*)(g + e);
    float4 uv = *(const float4*)(u + e);
    float4 v;
    v.x = gv.x / (1.f + __expf(-gv.x)) * uv.x;
    v.y = gv.y / (1.f + __expf(-gv.y)) * uv.y;
    v.z = gv.z / (1.f + __expf(-gv.z)) * uv.z;
    v.w = gv.w / (1.f + __expf(-gv.w)) * uv.w;
    split_store(y + row * (2 * INTER_), k, v);
}

// ---------------- RMSNorm (fused hi/lo split output) ----------------
__global__ __launch_bounds__(256)
void rmsnorm_conv(const float* __restrict__ x, const float* __restrict__ w,
                  __nv_bfloat16* __restrict__ y) {
    int row = blockIdx.x, tid = threadIdx.x;
    const float4* xr = (const float4*)(x + (size_t)row * HIDDEN_);
    float4 v0 = xr[tid], v1 = xr[tid + 256];
    float ss = v0.x*v0.x + v0.y*v0.y + v0.z*v0.z + v0.w*v0.w
             + v1.x*v1.x + v1.y*v1.y + v1.z*v1.z + v1.w*v1.w;
    #pragma unroll
    for (int o = 16; o > 0; o >>= 1) ss += __shfl_xor_sync(0xffffffffu, ss, o);
    __shared__ float red[8];
    if ((tid & 31) == 0) red[tid >> 5] = ss;
    __syncthreads();
    float tot = 0.f;
    #pragma unroll
    for (int i = 0; i < 8; i++) tot += red[i];
    float inv = rsqrtf(tot / (float)HIDDEN_ + 1e-5f);
    const float4* wr = (const float4*)w;
    float4 w0 = wr[tid], w1 = wr[tid + 256];
    float4 o0, o1;
    o0.x = v0.x*inv*w0.x; o0.y = v0.y*inv*w0.y; o0.z = v0.z*inv*w0.z; o0.w = v0.w*inv*w0.w;
    o1.x = v1.x*inv*w1.x; o1.y = v1.y*inv*w1.y; o1.z = v1.z*inv*w1.z; o1.w = v1.w*inv*w1.w;
    __nv_bfloat16* rb = y + (size_t)row * (2 * HIDDEN_);
    split_store(rb, tid * 4, o0);
    split_store(rb, tid * 4 + 1024, o1);
}

// ---------------- segment ids ----------------
__global__ void seg_kernel(const int* __restrict__ cuq, const int* __restrict__ cuk,
                           int ncu_q, int ncu_k, int* __restrict__ segq, int* __restrict__ segk) {
    int p = blockIdx.x * blockDim.x + threadIdx.x;
    if (p < QLEN) {
        int s = 0;
        for (int i = 1; i < ncu_q; i++) s += (cuq[i] <= p);
        segq[p] = s;
    }
    if (p < KLEN) {
        int s = 0;
        for (int i = 1; i < ncu_k; i++) s += (cuk[i] <= p);
        segk[p] = s;
    }
}

// ---------------- HMMA bf16x3 GEMM: C = A * B^T (+Res) ----------------
// Converted row: per 32-elem chunk, 64 bf16 = [Ah0 Ah1 | Al0 Al1] at bytes {0,32,64,96}.
// Tile 128x128, 8 warps (2M x 4N), warp tile 64x32 via mma.sync.m16n8k16.
// Fragment-reuse schedule per chunk: persist Bh0,Bh1; loop A groups:
//   Ah0 x (Bh0, Bl0), Ah1 x (Bh1, Bl1), Al0 x Bh0, Al1 x Bh1
// = AhBh + AhBl + AlBh, 96 MMAs, 96 reg-loads (vs 144 before).
// One __syncthreads per chunk (bottom barrier redundant: iter j's prefetch
// into stage (j-1)%3 is issued after iter j's top sync, which orders all
// warps past their iter j-1 reads).
#define NSTG 3
#define ROWSPAN 144
#define OP_BYTES (128 * ROWSPAN)       // 18432
#define STG_BYTES (2 * OP_BYTES)       // 36864

__device__ __forceinline__ void stage_load(uint32_t sbase, int s, const char* Ab,
                                           const char* Bb, size_t rowB, int tid) {
    uint32_t so = sbase + s * STG_BYTES;
    #pragma unroll
    for (int it = 0; it < 8; it++) {
        int lin = it * 256 + tid;          // 0..2047 units of 16B
        int op  = lin >> 10;               // 0: A, 1: B
        int u   = lin & 1023;
        int row = u >> 3;
        int cb  = (u & 7) << 4;
        uint32_t dst = so + op * OP_BYTES + row * ROWSPAN + cb;
        const char* src = (op ? Bb : Ab) + (size_t)row * rowB + cb;
        asm volatile("cp.async.cg.shared.global [%0], [%1], 16;" :: "r"(dst), "l"(src));
    }
    asm volatile("cp.async.commit_group;" ::: "memory");
}

__device__ __forceinline__ void mma_bf16(float c[4], uint32_t a0, uint32_t a1,
                                         uint32_t a2, uint32_t a3,
                                         uint32_t b0, uint32_t b1) {
    asm volatile(
        "mma.sync.aligned.m16n8k16.row.col.f32.bf16.bf16.f32 "
        "{%0,%1,%2,%3}, {%4,%5,%6,%7}, {%8,%9}, {%0,%1,%2,%3};"
        : "+f"(c[0]), "+f"(c[1]), "+f"(c[2]), "+f"(c[3])
        : "r"(a0), "r"(a1), "r"(a2), "r"(a3), "r"(b0), "r"(b1));
}

__global__ __launch_bounds__(256)
void gemm_mma(const __nv_bfloat16* __restrict__ Ac, const __nv_bfloat16* __restrict__ Bc,
              const float* __restrict__ Res, float* __restrict__ C, int M, int N, int K) {
    extern __shared__ __align__(128) char smem[];
    uint32_t sbase = smem_to_u32(smem);
    int tid = threadIdx.x, wid = tid >> 5, lane = tid & 31;
    int g = lane >> 2, t = lane & 3;
    int wm = wid >> 2, wn = wid & 3;      // warp grid 2(M) x 4(N)
    int m0 = blockIdx.y * 128, n0 = blockIdx.x * 128;
    size_t rowB = (size_t)K * 4;          // bytes per converted row (2K bf16)

    float acc[4][4][4];
    #pragma unroll
    for (int i = 0; i < 4; i++)
        #pragma unroll
        for (int j = 0; j < 4; j++)
            #pragma unroll
            for (int q = 0; q < 4; q++) acc[i][j][q] = 0.f;

    const char* Ab0 = (const char*)Ac + (size_t)m0 * rowB;
    const char* Bb0 = (const char*)Bc + (size_t)n0 * rowB;
    int niters = K >> 5;                  // one 128B chunk per iter

    stage_load(sbase, 0, Ab0, Bb0, rowB, tid);
    stage_load(sbase, 1, Ab0 + 128, Bb0 + 128, rowB, tid);

    for (int j = 0; j < niters; j++) {
        if (j < niters - 1) asm volatile("cp.async.wait_group 1;" ::: "memory");
        else                asm volatile("cp.async.wait_group 0;" ::: "memory");
        __syncthreads();

        int jn = j + 2;
        if (jn < niters)
            stage_load(sbase, jn % NSTG, Ab0 + (size_t)jn * 128, Bb0 + (size_t)jn * 128, rowB, tid);

        const char* sA = smem + (j % NSTG) * STG_BYTES;
        const char* sB = sA + OP_BYTES;

        // persist B-hi fragments for both k-halves
        uint32_t bh[2][4][2];
        #pragma unroll
        for (int h = 0; h < 2; h++)
            #pragma unroll
            for (int ni = 0; ni < 4; ni++) {
                const char* bp = sB + (wn * 32 + ni * 8 + g) * ROWSPAN + h * 32 + t * 4;
                bh[h][ni][0] = *(const uint32_t*)(bp);
                bh[h][ni][1] = *(const uint32_t*)(bp + 16);
            }

        #pragma unroll
        for (int agrp = 0; agrp < 4; agrp++) {
            int ab = agrp * 32;
            uint32_t af[4][4];
            #pragma unroll
            for (int mi = 0; mi < 4; mi++) {
                const char* ap = sA + (wm * 64 + mi * 16 + g) * ROWSPAN + ab + t * 4;
                af[mi][0] = *(const uint32_t*)(ap);
                af[mi][1] = *(const uint32_t*)(ap + 8 * ROWSPAN);
                af[mi][2] = *(const uint32_t*)(ap + 16);
                af[mi][3] = *(const uint32_t*)(ap + 8 * ROWSPAN + 16);
            }
            int bsel = agrp & 1;   // Ah0,Al0 pair with Bh0; Ah1,Al1 with Bh1
            #pragma unroll
            for (int mi = 0; mi < 4; mi++)
                #pragma unroll
                for (int ni = 0; ni < 4; ni++)
                    mma_bf16(acc[mi][ni], af[mi][0], af[mi][1], af[mi][2], af[mi][3],
                             bh[bsel][ni][0], bh[bsel][ni][1]);
            if (agrp < 2) {        // Ah x Bl cross term
                uint32_t bl[4][2];
                #pragma unroll
                for (int ni = 0; ni < 4; ni++) {
                    const char* bp = sB + (wn * 32 + ni * 8 + g) * ROWSPAN + 64 + agrp * 32 + t * 4;
                    bl[ni][0] = *(const uint32_t*)(bp);
                    bl[ni][1] = *(const uint32_t*)(bp + 16);
                }
                #pragma unroll
                for (int mi = 0; mi < 4; mi++)
                    #pragma unroll
                    for (int ni = 0; ni < 4; ni++)
                        mma_bf16(acc[mi][ni], af[mi][0], af[mi][1], af[mi][2], af[mi][3],
                                 bl[ni][0], bl[ni][1]);
            }
        }
    }

    // epilogue: warp writes its 64x32 region
    #pragma unroll
    for (int mi = 0; mi < 4; mi++) {
        int grow0 = m0 + wm * 64 + mi * 16 + g;
        int grow1 = grow0 + 8;
        #pragma unroll
        for (int ni = 0; ni < 4; ni++) {
            int gcol = n0 + wn * 32 + ni * 8 + t * 2;
            float2 v0 = make_float2(acc[mi][ni][0], acc[mi][ni][1]);
            float2 v1 = make_float2(acc[mi][ni][2], acc[mi][ni][3]);
            if (Res) {
                float2 r0 = *(const float2*)(Res + (size_t)grow0 * N + gcol);
                float2 r1 = *(const float2*)(Res + (size_t)grow1 * N + gcol);
                v0.x += r0.x; v0.y += r0.y;
                v1.x += r1.x; v1.y += r1.y;
            }
            *(float2*)(C + (size_t)grow0 * N + gcol) = v0;
            *(float2*)(C + (size_t)grow1 * N + gcol) = v1;
        }
    }
}

// ---------------- flash attention (unchanged, known-passing) ----------------
__global__ __launch_bounds__(64)
void attn_kernel(const float* __restrict__ Qp, const float* __restrict__ Kp,
                 const float* __restrict__ Vp, const int* __restrict__ segq,
                 const int* __restrict__ segk, const int* __restrict__ cuk,
                 float* __restrict__ Op, int q_len, int k_len)
{
    const int BQ = 64, BK_T = 64;
    const float scale = 0.125f;
    extern __shared__ float4 smbuf[];
    float4* Ks = smbuf;
    float4* Vs = smbuf + 1024;
    float4* Qs = smbuf + 2048;

    int qt = blockIdx.x, h = blockIdx.y, b = blockIdx.z;
    int kvh = h / KVREP;
    int tid = threadIdx.x;
    int qrow = qt * BQ + tid;
    int off = (k_len > q_len) ? (k_len - q_len) : 0;

    {
        const float4* src = (const float4*)(Qp + ((size_t)(b * q_len + qrow) * NH + h) * HD);
        #pragma unroll
        for (int d4 = 0; d4 < 16; d4++) {
            float4 v = src[d4];
            v.x *= scale; v.y *= scale; v.z *= scale; v.w *= scale;
            Qs[tid * 17 + d4] = v;
        }
    }

    int myseg = segq[qrow];
    int kstart = (cuk[segq[qt * BQ]] / BK_T) * BK_T;
    int kend = min(k_len, qt * BQ + BQ + off);

    float4 acc4[16];
    #pragma unroll
    for (int i = 0; i < 16; i++) acc4[i] = make_float4(0.f, 0.f, 0.f, 0.f);
    float m = -1e30f, l = 0.f;

    for (int k0 = kstart; k0 < kend; k0 += BK_T) {
        __syncthreads();
        for (int i = tid; i < BK_T * 16; i += 64) {
            int r = i >> 4, d4 = i & 15;
            size_t base = ((size_t)(b * k_len + k0 + r) * NKV + kvh) * HD;
            Ks[r * 16 + d4] = ((const float4*)(Kp + base))[d4];
            Vs[r * 16 + d4] = ((const float4*)(Vp + base))[d4];
        }
        __syncthreads();

        float s[BK_T];
        #pragma unroll
        for (int kk = 0; kk < BK_T; kk++) s[kk] = 0.f;
        for (int d4 = 0; d4 < 16; d4++) {
            float4 q4 = Qs[tid * 17 + d4];
            #pragma unroll
            for (int kk = 0; kk < BK_T; kk++) {
                float4 k4 = Ks[kk * 16 + d4];
                s[kk] += q4.x * k4.x + q4.y * k4.y + q4.z * k4.z + q4.w * k4.w;
            }
        }

        float tmax = -1e30f;
        #pragma unroll
        for (int kk = 0; kk < BK_T; kk++) {
            int kg = k0 + kk;
            bool ok = (kg < k_len) && (kg <= qrow + off) && (segk[kg] == myseg);
            s[kk] = ok ? s[kk] : -1e30f;
            tmax = fmaxf(tmax, s[kk]);
        }
        if (tmax > -1e29f) {
            float mnew = fmaxf(m, tmax);
            float corr = __expf(m - mnew);
            l *= corr;
            #pragma unroll
            for (int i = 0; i < 16; i++) {
                acc4[i].x *= corr; acc4[i].y *= corr;
                acc4[i].z *= corr; acc4[i].w *= corr;
            }
            #pragma unroll
            for (int kk = 0; kk < BK_T; kk++) {
                float p = __expf(s[kk] - mnew);
                l += p;
                #pragma unroll
                for (int d4 = 0; d4 < 16; d4++) {
                    float4 v4 = Vs[kk * 16 + d4];
                    acc4[d4].x += p * v4.x; acc4[d4].y += p * v4.y;
                    acc4[d4].z += p * v4.z; acc4[d4].w += p * v4.w;
                }
            }
            m = mnew;
        }
    }

    float inv = 1.f / l;
    float4* dst = (float4*)(Op + ((size_t)(b * q_len + qrow) * NH + h) * HD);
    #pragma unroll
    for (int d4 = 0; d4 < 16; d4++) {
        float4 v = acc4[d4];
        v.x *= inv; v.y *= inv; v.z *= inv; v.w *= inv;
        dst[d4] = v;
    }
}

// ---------------- launch ----------------
extern "C" void kernel_launch(void* const* d_in, const int* in_sizes, int n_in,
                              void* d_out, int out_size)
{
    const float* hs   = (const float*)d_in[0];
    const float* kst  = (const float*)d_in[1];
    const float* vst  = (const float*)d_in[2];
    const float* wln1 = (const float*)d_in[4];
    const float* wln2 = (const float*)d_in[5];
    const float* wq   = (const float*)d_in[6];
    const float* wo   = (const float*)d_in[7];
    const float* wg   = (const float*)d_in[8];
    const float* wu   = (const float*)d_in[9];
    const float* wd   = (const float*)d_in[10];
    const int* cuq    = (const int*)d_in[11];
    const int* cuk    = (const int*)d_in[12];
    int ncu_q = in_sizes[11], ncu_k = in_sizes[12];
    float* out = (float*)d_out;

    float *qproj, *attn, *hidden, *gate, *up;
    int *segq, *segk;
    __nv_bfloat16 *cwq, *cwo, *cwg, *cwu, *cwd, *cn1, *cat, *cn2, *cac;
    cudaGetSymbolAddress((void**)&qproj,  g_qproj);
    cudaGetSymbolAddress((void**)&attn,   g_attn);
    cudaGetSymbolAddress((void**)&hidden, g_hidden);
    cudaGetSymbolAddress((void**)&gate,   g_gate);
    cudaGetSymbolAddress((void**)&up,     g_up);
    cudaGetSymbolAddress((void**)&segq,   g_segq);
    cudaGetSymbolAddress((void**)&segk,   g_segk);
    cudaGetSymbolAddress((void**)&cwq, c_wq);
    cudaGetSymbolAddress((void**)&cwo, c_wo);
    cudaGetSymbolAddress((void**)&cwg, c_wg);
    cudaGetSymbolAddress((void**)&cwu, c_wu);
    cudaGetSymbolAddress((void**)&cwd, c_wd);
    cudaGetSymbolAddress((void**)&cn1, c_normed);
    cudaGetSymbolAddress((void**)&cat, c_attn);
    cudaGetSymbolAddress((void**)&cn2, c_normed2);
    cudaGetSymbolAddress((void**)&cac, c_act);

    const int GEMM_SMEM = NSTG * STG_BYTES;   // 110592
    cudaFuncSetAttribute(gemm_mma, cudaFuncAttributeMaxDynamicSharedMemorySize, GEMM_SMEM);
    const int ATTN_SMEM = (1024 + 1024 + 64 * 17) * 16;
    cudaFuncSetAttribute(attn_kernel, cudaFuncAttributeMaxDynamicSharedMemorySize, ATTN_SMEM);

    // weight conversions (hi/lo bf16 split, interleaved)
    convert_split<<< (HIDDEN_ * HIDDEN_) / 1024, 256 >>>(wq, cwq, 11);
    convert_split<<< (HIDDEN_ * HIDDEN_) / 1024, 256 >>>(wo, cwo, 11);
    convert_split<<< (INTER_  * HIDDEN_) / 1024, 256 >>>(wg, cwg, 11);
    convert_split<<< (INTER_  * HIDDEN_) / 1024, 256 >>>(wu, cwu, 11);
    convert_split<<< (HIDDEN_ * INTER_ ) / 1024, 256 >>>(wd, cwd, 13);

    // ln1 (fused split)
    rmsnorm_conv<<<MROWS, 256>>>(hs, wln1, cn1);
    // q projection
    gemm_mma<<<dim3(HIDDEN_ / 128, MROWS / 128), 256, GEMM_SMEM>>>(
        cn1, cwq, nullptr, qproj, MROWS, HIDDEN_, HIDDEN_);
    // segment ids
    seg_kernel<<<(QLEN + 255) / 256, 256>>>(cuq, cuk, ncu_q, ncu_k, segq, segk);
    // attention
    attn_kernel<<<dim3(QLEN / 64, NH, B_), 64, ATTN_SMEM>>>(
        qproj, kst, vst, segq, segk, cuk, attn, QLEN, KLEN);
    // o projection + residual
    convert_split<<< (MROWS * HIDDEN_) / 1024, 256 >>>(attn, cat, 11);
    gemm_mma<<<dim3(HIDDEN_ / 128, MROWS / 128), 256, GEMM_SMEM>>>(
        cat, cwo, hs, hidden, MROWS, HIDDEN_, HIDDEN_);
    // ln2 (fused split)
    rmsnorm_conv<<<MROWS, 256>>>(hidden, wln2, cn2);
    // gate / up projections
    gemm_mma<<<dim3(INTER_ / 128, MROWS / 128), 256, GEMM_SMEM>>>(
        cn2, cwg, nullptr, gate, MROWS, INTER_, HIDDEN_);
    gemm_mma<<<dim3(INTER_ / 128, MROWS / 128), 256, GEMM_SMEM>>>(
        cn2, cwu, nullptr, up, MROWS, INTER_, HIDDEN_);
    // silu(gate)*up (fused split)
    silu_conv<<< (int)(((size_t)MROWS * INTER_) / 1024), 256 >>>(gate, up, cac);
    // down projection + residual -> out
    gemm_mma<<<dim3(HIDDEN_ / 128, MROWS / 128), 256, GEMM_SMEM>>>(
        cac, cwd, hidden, out, MROWS, HIDDEN_, INTER_);
}

// round 16
// speedup vs baseline: 2.2408x; 1.0656x over previous
#include <cuda_runtime.h>
#include <cuda_bf16.h>
#include <cstdint>
#include <math.h>

// ---------------- problem constants ----------------
#define B_      2
#define QLEN    2048
#define KLEN    2048
#define HIDDEN_ 2048
#define NH      32
#define NKV     8
#define HD      64
#define KVREP   (NH / NKV)
#define INTER_  8192
#define MROWS   (B_ * QLEN)     // 4096

// ---------------- scratch (device globals) ----------------
__device__ float g_normed [(size_t)MROWS * HIDDEN_];
__device__ float g_qproj  [(size_t)MROWS * HIDDEN_];
__device__ float g_attn   [(size_t)MROWS * HIDDEN_];
__device__ float g_hidden [(size_t)MROWS * HIDDEN_];
__device__ float g_normed2[(size_t)MROWS * HIDDEN_];
__device__ float g_gate   [(size_t)MROWS * INTER_];
__device__ float g_up     [(size_t)MROWS * INTER_];
__device__ int   g_segq[QLEN];
__device__ int   g_segk[KLEN];

// ---------------- helpers ----------------
__device__ __forceinline__ uint32_t smem_to_u32(const void* p) {
    uint32_t a;
    asm("{ .reg .u64 t; cvta.to.shared.u64 t, %1; cvt.u32.u64 %0, t; }" : "=r"(a) : "l"(p));
    return a;
}

// ---------------- RMSNorm (plain fp32 out) ----------------
__global__ __launch_bounds__(256)
void rmsnorm_kernel(const float* __restrict__ x, const float* __restrict__ w,
                    float* __restrict__ y) {
    int row = blockIdx.x, tid = threadIdx.x;
    const float4* xr = (const float4*)(x + (size_t)row * HIDDEN_);
    float4 v0 = xr[tid], v1 = xr[tid + 256];
    float ss = v0.x*v0.x + v0.y*v0.y + v0.z*v0.z + v0.w*v0.w
             + v1.x*v1.x + v1.y*v1.y + v1.z*v1.z + v1.w*v1.w;
    #pragma unroll
    for (int o = 16; o > 0; o >>= 1) ss += __shfl_xor_sync(0xffffffffu, ss, o);
    __shared__ float red[8];
    if ((tid & 31) == 0) red[tid >> 5] = ss;
    __syncthreads();
    float tot = 0.f;
    #pragma unroll
    for (int i = 0; i < 8; i++) tot += red[i];
    float inv = rsqrtf(tot / (float)HIDDEN_ + 1e-5f);
    const float4* wr = (const float4*)w;
    float4 w0 = wr[tid], w1 = wr[tid + 256];
    float4 o0, o1;
    o0.x = v0.x*inv*w0.x; o0.y = v0.y*inv*w0.y; o0.z = v0.z*inv*w0.z; o0.w = v0.w*inv*w0.w;
    o1.x = v1.x*inv*w1.x; o1.y = v1.y*inv*w1.y; o1.z = v1.z*inv*w1.z; o1.w = v1.w*inv*w1.w;
    float4* yr = (float4*)(y + (size_t)row * HIDDEN_);
    yr[tid]       = o0;
    yr[tid + 256] = o1;
}

// ---------------- silu(gate)*up (plain fp32 out) ----------------
__global__ __launch_bounds__(256)
void silu_mul_kernel(const float* __restrict__ g, const float* __restrict__ u,
                     float* __restrict__ o, size_t n4) {
    size_t i = (size_t)blockIdx.x * blockDim.x + threadIdx.x;
    if (i >= n4) return;
    float4 gv = ((const float4*)g)[i];
    float4 uv = ((const float4*)u)[i];
    float4 ov;
    ov.x = gv.x / (1.f + __expf(-gv.x)) * uv.x;
    ov.y = gv.y / (1.f + __expf(-gv.y)) * uv.y;
    ov.z = gv.z / (1.f + __expf(-gv.z)) * uv.z;
    ov.w = gv.w / (1.f + __expf(-gv.w)) * uv.w;
    ((float4*)o)[i] = ov;
}

// ---------------- segment ids ----------------
__global__ void seg_kernel(const int* __restrict__ cuq, const int* __restrict__ cuk,
                           int ncu_q, int ncu_k, int* __restrict__ segq, int* __restrict__ segk) {
    int p = blockIdx.x * blockDim.x + threadIdx.x;
    if (p < QLEN) {
        int s = 0;
        for (int i = 1; i < ncu_q; i++) s += (cuq[i] <= p);
        segq[p] = s;
    }
    if (p < KLEN) {
        int s = 0;
        for (int i = 1; i < ncu_k; i++) s += (cuk[i] <= p);
        segk[p] = s;
    }
}

// ---------------- 1xTF32 HMMA GEMM: C = A * B^T (+Res) ----------------
// A: [M][K] fp32 row-major, B: [N][K] fp32 row-major (read directly, no
// pre-conversion; fragments rounded to tf32 with cvt.rna after LDS).
// Tile 128x128, 8 warps (2M x 4N), warp tile 64x32 via mma.sync.m16n8k8.tf32.
// Chunk = 32 fp32 = 128B per row; 4 k-steps (k=8) per chunk; 64 MMA/chunk/warp.
// ROWSPAN=144 pad keeps fragment LDS perfectly bank-conflict-free (same
// address algebra as the proven bf16 version).
#define NSTG 3
#define ROWSPAN 144
#define OP_BYTES (128 * ROWSPAN)       // 18432
#define STG_BYTES (2 * OP_BYTES)       // 36864

__device__ __forceinline__ void stage_load(uint32_t sbase, int s, const char* Ab,
                                           const char* Bb, size_t rowB, int tid) {
    uint32_t so = sbase + s * STG_BYTES;
    #pragma unroll
    for (int it = 0; it < 8; it++) {
        int lin = it * 256 + tid;          // 0..2047 units of 16B
        int op  = lin >> 10;               // 0: A, 1: B
        int u   = lin & 1023;
        int row = u >> 3;
        int cb  = (u & 7) << 4;
        uint32_t dst = so + op * OP_BYTES + row * ROWSPAN + cb;
        const char* src = (op ? Bb : Ab) + (size_t)row * rowB + cb;
        asm volatile("cp.async.cg.shared.global [%0], [%1], 16;" :: "r"(dst), "l"(src));
    }
    asm volatile("cp.async.commit_group;" ::: "memory");
}

__device__ __forceinline__ uint32_t ld_tf32(const char* p) {
    float f = *(const float*)p;
    uint32_t r;
    asm("cvt.rna.tf32.f32 %0, %1;" : "=r"(r) : "f"(f));
    return r;
}

__device__ __forceinline__ void mma_tf32(float c[4], uint32_t a0, uint32_t a1,
                                         uint32_t a2, uint32_t a3,
                                         uint32_t b0, uint32_t b1) {
    asm volatile(
        "mma.sync.aligned.m16n8k8.row.col.f32.tf32.tf32.f32 "
        "{%0,%1,%2,%3}, {%4,%5,%6,%7}, {%8,%9}, {%0,%1,%2,%3};"
        : "+f"(c[0]), "+f"(c[1]), "+f"(c[2]), "+f"(c[3])
        : "r"(a0), "r"(a1), "r"(a2), "r"(a3), "r"(b0), "r"(b1));
}

__global__ __launch_bounds__(256)
void gemm_mma(const float* __restrict__ Ac, const float* __restrict__ Bc,
              const float* __restrict__ Res, float* __restrict__ C, int M, int N, int K) {
    extern __shared__ __align__(128) char smem[];
    uint32_t sbase = smem_to_u32(smem);
    int tid = threadIdx.x, wid = tid >> 5, lane = tid & 31;
    int g = lane >> 2, t = lane & 3;
    int wm = wid >> 2, wn = wid & 3;      // warp grid 2(M) x 4(N)
    int m0 = blockIdx.y * 128, n0 = blockIdx.x * 128;
    size_t rowB = (size_t)K * 4;          // bytes per fp32 row

    float acc[4][4][4];
    #pragma unroll
    for (int i = 0; i < 4; i++)
        #pragma unroll
        for (int j = 0; j < 4; j++)
            #pragma unroll
            for (int q = 0; q < 4; q++) acc[i][j][q] = 0.f;

    const char* Ab0 = (const char*)Ac + (size_t)m0 * rowB;
    const char* Bb0 = (const char*)Bc + (size_t)n0 * rowB;
    int niters = K >> 5;                  // one 128B (32-elem) chunk per iter

    stage_load(sbase, 0, Ab0, Bb0, rowB, tid);
    stage_load(sbase, 1, Ab0 + 128, Bb0 + 128, rowB, tid);

    for (int j = 0; j < niters; j++) {
        if (j < niters - 1) asm volatile("cp.async.wait_group 1;" ::: "memory");
        else                asm volatile("cp.async.wait_group 0;" ::: "memory");
        __syncthreads();

        int jn = j + 2;
        if (jn < niters)
            stage_load(sbase, jn % NSTG, Ab0 + (size_t)jn * 128, Bb0 + (size_t)jn * 128, rowB, tid);

        const char* sA = smem + (j % NSTG) * STG_BYTES;
        const char* sB = sA + OP_BYTES;

        #pragma unroll
        for (int ks = 0; ks < 4; ks++) {
            int kb = ks * 32;             // byte offset of this k-step (8 fp32)
            uint32_t bf[4][2];
            #pragma unroll
            for (int ni = 0; ni < 4; ni++) {
                const char* bp = sB + (wn * 32 + ni * 8 + g) * ROWSPAN + kb + t * 4;
                bf[ni][0] = ld_tf32(bp);
                bf[ni][1] = ld_tf32(bp + 16);
            }
            uint32_t af[4][4];
            #pragma unroll
            for (int mi = 0; mi < 4; mi++) {
                const char* ap = sA + (wm * 64 + mi * 16 + g) * ROWSPAN + kb + t * 4;
                af[mi][0] = ld_tf32(ap);
                af[mi][1] = ld_tf32(ap + 8 * ROWSPAN);
                af[mi][2] = ld_tf32(ap + 16);
                af[mi][3] = ld_tf32(ap + 8 * ROWSPAN + 16);
            }
            #pragma unroll
            for (int mi = 0; mi < 4; mi++)
                #pragma unroll
                for (int ni = 0; ni < 4; ni++)
                    mma_tf32(acc[mi][ni], af[mi][0], af[mi][1], af[mi][2], af[mi][3],
                             bf[ni][0], bf[ni][1]);
        }
    }

    // epilogue: warp writes its 64x32 region
    #pragma unroll
    for (int mi = 0; mi < 4; mi++) {
        int grow0 = m0 + wm * 64 + mi * 16 + g;
        int grow1 = grow0 + 8;
        #pragma unroll
        for (int ni = 0; ni < 4; ni++) {
            int gcol = n0 + wn * 32 + ni * 8 + t * 2;
            float2 v0 = make_float2(acc[mi][ni][0], acc[mi][ni][1]);
            float2 v1 = make_float2(acc[mi][ni][2], acc[mi][ni][3]);
            if (Res) {
                float2 r0 = *(const float2*)(Res + (size_t)grow0 * N + gcol);
                float2 r1 = *(const float2*)(Res + (size_t)grow1 * N + gcol);
                v0.x += r0.x; v0.y += r0.y;
                v1.x += r1.x; v1.y += r1.y;
            }
            *(float2*)(C + (size_t)grow0 * N + gcol) = v0;
            *(float2*)(C + (size_t)grow1 * N + gcol) = v1;
        }
    }
}

// ---------------- flash attention (unchanged, known-passing) ----------------
__global__ __launch_bounds__(64)
void attn_kernel(const float* __restrict__ Qp, const float* __restrict__ Kp,
                 const float* __restrict__ Vp, const int* __restrict__ segq,
                 const int* __restrict__ segk, const int* __restrict__ cuk,
                 float* __restrict__ Op, int q_len, int k_len)
{
    const int BQ = 64, BK_T = 64;
    const float scale = 0.125f;
    extern __shared__ float4 smbuf[];
    float4* Ks = smbuf;
    float4* Vs = smbuf + 1024;
    float4* Qs = smbuf + 2048;

    int qt = blockIdx.x, h = blockIdx.y, b = blockIdx.z;
    int kvh = h / KVREP;
    int tid = threadIdx.x;
    int qrow = qt * BQ + tid;
    int off = (k_len > q_len) ? (k_len - q_len) : 0;

    {
        const float4* src = (const float4*)(Qp + ((size_t)(b * q_len + qrow) * NH + h) * HD);
        #pragma unroll
        for (int d4 = 0; d4 < 16; d4++) {
            float4 v = src[d4];
            v.x *= scale; v.y *= scale; v.z *= scale; v.w *= scale;
            Qs[tid * 17 + d4] = v;
        }
    }

    int myseg = segq[qrow];
    int kstart = (cuk[segq[qt * BQ]] / BK_T) * BK_T;
    int kend = min(k_len, qt * BQ + BQ + off);

    float4 acc4[16];
    #pragma unroll
    for (int i = 0; i < 16; i++) acc4[i] = make_float4(0.f, 0.f, 0.f, 0.f);
    float m = -1e30f, l = 0.f;

    for (int k0 = kstart; k0 < kend; k0 += BK_T) {
        __syncthreads();
        for (int i = tid; i < BK_T * 16; i += 64) {
            int r = i >> 4, d4 = i & 15;
            size_t base = ((size_t)(b * k_len + k0 + r) * NKV + kvh) * HD;
            Ks[r * 16 + d4] = ((const float4*)(Kp + base))[d4];
            Vs[r * 16 + d4] = ((const float4*)(Vp + base))[d4];
        }
        __syncthreads();

        float s[BK_T];
        #pragma unroll
        for (int kk = 0; kk < BK_T; kk++) s[kk] = 0.f;
        for (int d4 = 0; d4 < 16; d4++) {
            float4 q4 = Qs[tid * 17 + d4];
            #pragma unroll
            for (int kk = 0; kk < BK_T; kk++) {
                float4 k4 = Ks[kk * 16 + d4];
                s[kk] += q4.x * k4.x + q4.y * k4.y + q4.z * k4.z + q4.w * k4.w;
            }
        }

        float tmax = -1e30f;
        #pragma unroll
        for (int kk = 0; kk < BK_T; kk++) {
            int kg = k0 + kk;
            bool ok = (kg < k_len) && (kg <= qrow + off) && (segk[kg] == myseg);
            s[kk] = ok ? s[kk] : -1e30f;
            tmax = fmaxf(tmax, s[kk]);
        }
        if (tmax > -1e29f) {
            float mnew = fmaxf(m, tmax);
            float corr = __expf(m - mnew);
            l *= corr;
            #pragma unroll
            for (int i = 0; i < 16; i++) {
                acc4[i].x *= corr; acc4[i].y *= corr;
                acc4[i].z *= corr; acc4[i].w *= corr;
            }
            #pragma unroll
            for (int kk = 0; kk < BK_T; kk++) {
                float p = __expf(s[kk] - mnew);
                l += p;
                #pragma unroll
                for (int d4 = 0; d4 < 16; d4++) {
                    float4 v4 = Vs[kk * 16 + d4];
                    acc4[d4].x += p * v4.x; acc4[d4].y += p * v4.y;
                    acc4[d4].z += p * v4.z; acc4[d4].w += p * v4.w;
                }
            }
            m = mnew;
        }
    }

    float inv = 1.f / l;
    float4* dst = (float4*)(Op + ((size_t)(b * q_len + qrow) * NH + h) * HD);
    #pragma unroll
    for (int d4 = 0; d4 < 16; d4++) {
        float4 v = acc4[d4];
        v.x *= inv; v.y *= inv; v.z *= inv; v.w *= inv;
        dst[d4] = v;
    }
}

// ---------------- launch ----------------
extern "C" void kernel_launch(void* const* d_in, const int* in_sizes, int n_in,
                              void* d_out, int out_size)
{
    const float* hs   = (const float*)d_in[0];
    const float* kst  = (const float*)d_in[1];
    const float* vst  = (const float*)d_in[2];
    const float* wln1 = (const float*)d_in[4];
    const float* wln2 = (const float*)d_in[5];
    const float* wq   = (const float*)d_in[6];
    const float* wo   = (const float*)d_in[7];
    const float* wg   = (const float*)d_in[8];
    const float* wu   = (const float*)d_in[9];
    const float* wd   = (const float*)d_in[10];
    const int* cuq    = (const int*)d_in[11];
    const int* cuk    = (const int*)d_in[12];
    int ncu_q = in_sizes[11], ncu_k = in_sizes[12];
    float* out = (float*)d_out;

    float *normed, *qproj, *attn, *hidden, *normed2, *gate, *up;
    int *segq, *segk;
    cudaGetSymbolAddress((void**)&normed,  g_normed);
    cudaGetSymbolAddress((void**)&qproj,   g_qproj);
    cudaGetSymbolAddress((void**)&attn,    g_attn);
    cudaGetSymbolAddress((void**)&hidden,  g_hidden);
    cudaGetSymbolAddress((void**)&normed2, g_normed2);
    cudaGetSymbolAddress((void**)&gate,    g_gate);
    cudaGetSymbolAddress((void**)&up,      g_up);
    cudaGetSymbolAddress((void**)&segq,    g_segq);
    cudaGetSymbolAddress((void**)&segk,    g_segk);

    const int GEMM_SMEM = NSTG * STG_BYTES;   // 110592
    cudaFuncSetAttribute(gemm_mma, cudaFuncAttributeMaxDynamicSharedMemorySize, GEMM_SMEM);
    const int ATTN_SMEM = (1024 + 1024 + 64 * 17) * 16;
    cudaFuncSetAttribute(attn_kernel, cudaFuncAttributeMaxDynamicSharedMemorySize, ATTN_SMEM);

    // 1) ln1
    rmsnorm_kernel<<<MROWS, 256>>>(hs, wln1, normed);
    // 2) q projection (tf32, weights read directly)
    gemm_mma<<<dim3(HIDDEN_ / 128, MROWS / 128), 256, GEMM_SMEM>>>(
        normed, wq, nullptr, qproj, MROWS, HIDDEN_, HIDDEN_);
    // 3) segment ids
    seg_kernel<<<(QLEN + 255) / 256, 256>>>(cuq, cuk, ncu_q, ncu_k, segq, segk);
    // 4) attention
    attn_kernel<<<dim3(QLEN / 64, NH, B_), 64, ATTN_SMEM>>>(
        qproj, kst, vst, segq, segk, cuk, attn, QLEN, KLEN);
    // 5) o projection + residual
    gemm_mma<<<dim3(HIDDEN_ / 128, MROWS / 128), 256, GEMM_SMEM>>>(
        attn, wo, hs, hidden, MROWS, HIDDEN_, HIDDEN_);
    // 6) ln2
    rmsnorm_kernel<<<MROWS, 256>>>(hidden, wln2, normed2);
    // 7) gate / up projections
    gemm_mma<<<dim3(INTER_ / 128, MROWS / 128), 256, GEMM_SMEM>>>(
        normed2, wg, nullptr, gate, MROWS, INTER_, HIDDEN_);
    gemm_mma<<<dim3(INTER_ / 128, MROWS / 128), 256, GEMM_SMEM>>>(
        normed2, wu, nullptr, up, MROWS, INTER_, HIDDEN_);
    // 8) silu(gate)*up (in place into gate)
    silu_mul_kernel<<<(unsigned)(((size_t)MROWS * INTER_ / 4 + 255) / 256), 256>>>(
        gate, up, gate, (size_t)MROWS * INTER_ / 4);
    // 9) down projection + residual -> out
    gemm_mma<<<dim3(HIDDEN_ / 128, MROWS / 128), 256, GEMM_SMEM>>>(
        gate, wd, hidden, out, MROWS, HIDDEN_, INTER_);
}